// round 15
// baseline (speedup 1.0000x reference)
#include <cuda_runtime.h>
#include <cuda_fp16.h>
#include <cstdint>

// ---------------------------------------------------------------------------
// BaseProtonet via mma.sync (HMMA). Round 15: round-14 base (103.1us) +
//  (a) closed-form swizzle addressing in the mainloop: for x = r*128 + c*16,
//      SWZ128(x) = r*128 + 32*(ks ^ kx) + 16*(chnk ^ bx) with kx,bx
//      lane-constant -> LDSM addresses = base_reg + imm (+1 XOR), replacing
//      the per-iteration SHF/LOP3/IADD swizzle chain;
//  (b) zero-C first MMA (C=RZ at ks==0) -> the 128 MOV acc-inits deleted.
// Core: BM=256 / 512 thr / grid=N/BM, 3-pass fp16 hi/lo split, hoisted B
// conversion kernel, explicit MLP=8 A-load hoist, pair-max argmax.
// inv_d = 64/(f2+p2-2*cross+64e-5); labels via per-row argmax (first index).
// ---------------------------------------------------------------------------

#define SWZ128(o) ((o) ^ (((o) >> 3) & 0x70))

constexpr int Dk = 64;
constexpr int Pn = 256;
constexpr int BM = 256;
constexpr int THREADS = 512;

constexpr int OFF_AHI  = 0;          // 256 rows x 128B = 32768
constexpr int OFF_ALO  = 32768;
constexpr int OFF_BHI  = 65536;      // 32768
constexpr int OFF_BLO  = 98304;      // 32768
constexpr int OFF_P2   = 131072;     // 1024
constexpr int OFF_F2   = 132096;     // 1024
constexpr int OFF_SBST = 133120;     // 2048
constexpr int OFF_SIDX = 135168;     // 2048
constexpr int SMEM_BYTES = 137216;   // 1 CTA/SM (16 warps)

// global scratch: [0,32768) Bhi swizzled | [32768,65536) Blo swizzled | [65536,+1024) p2
__device__ __align__(128) unsigned char g_bconv[66560];

__device__ __forceinline__ uint32_t smem_u32(const void* p) {
    uint32_t a;
    asm("{ .reg .u64 t; cvta.to.shared.u64 t, %1; cvt.u32.u64 %0, t; }" : "=r"(a) : "l"(p));
    return a;
}
__device__ __forceinline__ uint64_t gmem_u64(const void* p) {
    uint64_t a;
    asm("cvta.to.global.u64 %0, %1;" : "=l"(a) : "l"(p));
    return a;
}
__device__ __forceinline__ void cp_async16(uint32_t sdst, uint64_t gsrc) {
    asm volatile("cp.async.cg.shared.global [%0], [%1], 16;" :: "r"(sdst), "l"(gsrc) : "memory");
}
__device__ __forceinline__ void ldsm_x4(uint32_t r[4], uint32_t addr) {
    asm volatile("ldmatrix.sync.aligned.m8n8.x4.shared.b16 {%0,%1,%2,%3}, [%4];"
                 : "=r"(r[0]), "=r"(r[1]), "=r"(r[2]), "=r"(r[3]) : "r"(addr));
}
__device__ __forceinline__ void mma16816(float c[4], const uint32_t a[4],
                                         uint32_t b0, uint32_t b1) {
    asm volatile("mma.sync.aligned.m16n8k16.row.col.f32.f16.f16.f32 "
                 "{%0,%1,%2,%3}, {%4,%5,%6,%7}, {%8,%9}, {%0,%1,%2,%3};"
                 : "+f"(c[0]), "+f"(c[1]), "+f"(c[2]), "+f"(c[3])
                 : "r"(a[0]), "r"(a[1]), "r"(a[2]), "r"(a[3]), "r"(b0), "r"(b1));
}
// first-touch variant: C = 0 (ptxas materializes RZ) -> no acc zero-init MOVs
__device__ __forceinline__ void mma16816_z(float c[4], const uint32_t a[4],
                                           uint32_t b0, uint32_t b1) {
    asm volatile("mma.sync.aligned.m16n8k16.row.col.f32.f16.f16.f32 "
                 "{%0,%1,%2,%3}, {%4,%5,%6,%7}, {%8,%9}, {%10,%11,%12,%13};"
                 : "=f"(c[0]), "=f"(c[1]), "=f"(c[2]), "=f"(c[3])
                 : "r"(a[0]), "r"(a[1]), "r"(a[2]), "r"(a[3]), "r"(b0), "r"(b1),
                   "f"(0.f), "f"(0.f), "f"(0.f), "f"(0.f));
}
__device__ __forceinline__ uint32_t pack2(float x, float y) {
    __half hx = __float2half_rn(x), hy = __float2half_rn(y);
    return (uint32_t)__half_as_ushort(hx) | ((uint32_t)__half_as_ushort(hy) << 16);
}

// ---- Setup: convert protos -> fp16 hi/lo swizzled + p2 norms ---------------
__global__ void __launch_bounds__(256)
convert_B(const float* __restrict__ protos)
{
    const int tid = threadIdx.x;
    const int f4  = tid + blockIdx.x * 256;          // 0..4095
    {
        int row = f4 >> 4, k4 = f4 & 15;
        float4 v = ((const float4*)protos)[f4];
        float hx = __half2float(__float2half_rn(v.x));
        float hy = __half2float(__float2half_rn(v.y));
        float hz = __half2float(__float2half_rn(v.z));
        float hw = __half2float(__float2half_rn(v.w));
        uint2 hi = make_uint2(pack2(v.x, v.y), pack2(v.z, v.w));
        uint2 lo = make_uint2(pack2(v.x - hx, v.y - hy), pack2(v.z - hz, v.w - hw));
        uint32_t off = SWZ128((uint32_t)(row * 128 + k4 * 8));
        *(uint2*)(g_bconv + off)         = hi;
        *(uint2*)(g_bconv + 32768 + off) = lo;
    }
    if (blockIdx.x == 0) {   // p2 norms
        const float4* pr = (const float4*)protos + tid * 16;
        float q = 0.f;
        #pragma unroll
        for (int j = 0; j < 16; j++) {
            float4 v = pr[j];
            q = fmaf(v.x, v.x, q); q = fmaf(v.y, v.y, q);
            q = fmaf(v.z, v.z, q); q = fmaf(v.w, v.w, q);
        }
        ((float*)(g_bconv + 65536))[tid] = q;
    }
}

__global__ void __launch_bounds__(THREADS, 1)
BaseProtonet_hmma(const float* __restrict__ features,
                  const int*   __restrict__ proto_labels,
                  float* __restrict__ inv_out,
                  float* __restrict__ labels_out,
                  int labels_as_int)
{
    extern __shared__ char smem[];
    const uint32_t sbase = smem_u32(smem);
    const int tid  = threadIdx.x;
    const int wid  = tid >> 5;          // 0..15
    const int lane = tid & 31;

    float* p2s   = (float*)(smem + OFF_P2);
    float* f2s   = (float*)(smem + OFF_F2);
    float* sbest = (float*)(smem + OFF_SBST);   // [2][256]
    int*   sidx  = (int*)  (smem + OFF_SIDX);   // [2][256]

    const float* fb = features + (size_t)blockIdx.x * BM * Dk;

    // ---- Issue ALL A-tile loads first (cold DRAM, MLP=8 guaranteed) --------
    float4 va[8];
    {
        const float4* f4p = (const float4*)fb;
        #pragma unroll
        for (int i = 0; i < 8; i++)
            va[i] = f4p[tid + i * THREADS];
    }

    // ---- B + p2 copy (gmem scratch -> smem; L2-hot) -------------------------
    {
        const uint64_t gsrc = gmem_u64(g_bconv);
        #pragma unroll
        for (int i = 0; i < 8; i++)    // 64KB: Bhi+Blo contiguous
            cp_async16(sbase + OFF_BHI + i * 8192 + tid * 16,
                       gsrc + i * 8192 + tid * 16);
        if (tid < 64)                  // 1KB p2
            cp_async16(sbase + OFF_P2 + tid * 16, gsrc + 65536 + tid * 16);
        asm volatile("cp.async.commit_group;" ::: "memory");
    }

    // ---- Convert A tile (regs) -> fp16 hi/lo + f2 via shuffle reduction -----
    {
        #pragma unroll
        for (int i = 0; i < 8; i++) {
            int f4  = tid + i * THREADS;
            int row = f4 >> 4, k4 = f4 & 15;
            float4 v = va[i];
            float hx = __half2float(__float2half_rn(v.x));
            float hy = __half2float(__float2half_rn(v.y));
            float hz = __half2float(__float2half_rn(v.z));
            float hw = __half2float(__float2half_rn(v.w));
            uint2 hi = make_uint2(pack2(v.x, v.y), pack2(v.z, v.w));
            uint2 lo = make_uint2(pack2(v.x - hx, v.y - hy), pack2(v.z - hz, v.w - hw));
            uint32_t off = SWZ128((uint32_t)(row * 128 + k4 * 8));
            *(uint2*)(smem + OFF_AHI + off) = hi;
            *(uint2*)(smem + OFF_ALO + off) = lo;
            float s = v.x * v.x;
            s = fmaf(v.y, v.y, s);
            s = fmaf(v.z, v.z, s);
            s = fmaf(v.w, v.w, s);
            #pragma unroll
            for (int o = 8; o > 0; o >>= 1)
                s += __shfl_xor_sync(0xffffffffu, s, o);
            if ((tid & 15) == 0) f2s[row] = s;
        }
    }
    asm volatile("cp.async.wait_group 0;" ::: "memory");
    __syncthreads();

    // ---- Warp tiling: 8 row-groups x 2 col-halves ---------------------------
    const int wr0     = (wid >> 1) * 32;     // 0..224
    const int colhalf = wid & 1;
    const int g       = lane >> 2;
    const int q       = lane & 3;

    float srow[2][2];
    #pragma unroll
    for (int rt = 0; rt < 2; rt++) {
        srow[rt][0] = f2s[wr0 + rt * 16 + g]     + 64.f * 1e-5f;
        srow[rt][1] = f2s[wr0 + rt * 16 + g + 8] + 64.f * 1e-5f;
    }

    float best[2][2] = {{-1e30f, -1e30f}, {-1e30f, -1e30f}};
    int   bidx[2][2] = {{0, 0}, {0, 0}};

    const size_t row0 = (size_t)blockIdx.x * BM;

    float* outbase[2];
    #pragma unroll
    for (int rt = 0; rt < 2; rt++)
        outbase[rt] = inv_out + (row0 + wr0 + rt * 16 + g) * Pn + q * 2;

    const int bn_lane = (lane & 7) + ((lane >> 4) & 1) * 8;
    const int bc_lane = (lane >> 3) & 1;
    const int arow_lo = lane & 15;
    const int achnk   = lane >> 4;
    const bool do_out = (inv_out != nullptr);

    // ---- closed-form swizzle lane constants ---------------------------------
    // For x = r*128 + c*16 (c = 2*ks + chnk < 8):
    //   SWZ128(x) = r*128 + 32*(ks ^ ((r&7)>>1)) + 16*(chnk ^ (r&1))
    const uint32_t kxB32 = (uint32_t)(((bn_lane >> 1) & 3) * 32);
    const uint32_t bhi_base = sbase + OFF_BHI + bn_lane * 128
                            + (((bc_lane ^ bn_lane) & 1) * 16);
    const uint32_t kxA32 = (uint32_t)(((arow_lo >> 1) & 3) * 32);
    const uint32_t ahi_base = sbase + OFF_AHI + (wr0 + arow_lo) * 128
                            + (((achnk ^ arow_lo) & 1) * 16);

    #pragma unroll
    for (int ph = 0; ph < 2; ph++) {
        const int colbase = colhalf * 128 + ph * 64;
        const uint32_t bph_base = bhi_base + (uint32_t)colbase * 128;
        float acc[2][8][4];   // initialized by first-touch mma16816_z at ks==0

        // ---- preload A (ks=0) and B (it=0) ----------------------------------
        uint32_t ahi[2][4], alo[2][4];
        uint32_t bh[2][4], bl[2][4];
        #pragma unroll
        for (int rt = 0; rt < 2; rt++) {
            uint32_t offA = ahi_base + rt * 2048 + kxA32;
            ldsm_x4(ahi[rt], offA);
            ldsm_x4(alo[rt], offA + 32768);
        }
        {
            uint32_t offB = bph_base + kxB32;
            ldsm_x4(bh[0], offB);
            ldsm_x4(bl[0], offB + 32768);
        }

        // ---- flattened ks x tp loop with B double-buffer --------------------
        #pragma unroll
        for (int it = 0; it < 16; it++) {
            const int ks  = it >> 2;
            const int tp  = it & 3;
            const int cur = it & 1;
            const int nxt = cur ^ 1;
            if (it < 15) {
                const int ks2 = (it + 1) >> 2;
                const int tp2 = (it + 1) & 3;
                uint32_t offB = bph_base + (uint32_t)(tp2 * 2048)
                              + (kxB32 ^ (uint32_t)(32 * ks2));
                ldsm_x4(bh[nxt], offB);
                ldsm_x4(bl[nxt], offB + 32768);
            }
            const int t0 = tp * 2, t1 = t0 + 1;
            #pragma unroll
            for (int rt = 0; rt < 2; rt++) {
                if (ks == 0) {   // first touch of acc[rt][t0/t1]: C = 0
                    mma16816_z(acc[rt][t0], ahi[rt], bh[cur][0], bh[cur][1]);
                    mma16816_z(acc[rt][t1], ahi[rt], bh[cur][2], bh[cur][3]);
                } else {
                    mma16816(acc[rt][t0], ahi[rt], bh[cur][0], bh[cur][1]);
                    mma16816(acc[rt][t1], ahi[rt], bh[cur][2], bh[cur][3]);
                }
                mma16816(acc[rt][t0], ahi[rt], bl[cur][0], bl[cur][1]);
                mma16816(acc[rt][t1], ahi[rt], bl[cur][2], bl[cur][3]);
                mma16816(acc[rt][t0], alo[rt], bh[cur][0], bh[cur][1]);
                mma16816(acc[rt][t1], alo[rt], bh[cur][2], bh[cur][3]);
            }
            if (tp == 3 && ks < 3) {   // prefetch next-ks A fragments
                const uint32_t tA = kxA32 ^ (uint32_t)(32 * (ks + 1));
                #pragma unroll
                for (int rt = 0; rt < 2; rt++) {
                    uint32_t offA = ahi_base + rt * 2048 + tA;
                    ldsm_x4(ahi[rt], offA);
                    ldsm_x4(alo[rt], offA + 32768);
                }
            }
        }

        // ---- Epilogue for this phase: t outer, rt inner ----------------------
        #pragma unroll
        for (int t = 0; t < 8; t++) {
            const int col = colbase + t * 8 + q * 2;
            const float2 p2v = *(const float2*)&p2s[col];
            #pragma unroll
            for (int rt = 0; rt < 2; rt++) {
                float v0 = __fdividef(64.f, fmaf(-2.f, acc[rt][t][0], srow[rt][0] + p2v.x));
                float v1 = __fdividef(64.f, fmaf(-2.f, acc[rt][t][1], srow[rt][0] + p2v.y));
                float v2 = __fdividef(64.f, fmaf(-2.f, acc[rt][t][2], srow[rt][1] + p2v.x));
                float v3 = __fdividef(64.f, fmaf(-2.f, acc[rt][t][3], srow[rt][1] + p2v.y));
                if (do_out) {
                    __stcs((float2*)(outbase[rt] + colbase + t * 8),
                           make_float2(v0, v1));
                    __stcs((float2*)(outbase[rt] + 8 * Pn + colbase + t * 8),
                           make_float2(v2, v3));
                }
                float m01 = fmaxf(v0, v1);
                if (m01 > best[rt][0]) {
                    best[rt][0] = m01;
                    bidx[rt][0] = (v1 > v0) ? col + 1 : col;
                }
                float m23 = fmaxf(v2, v3);
                if (m23 > best[rt][1]) {
                    best[rt][1] = m23;
                    bidx[rt][1] = (v3 > v2) ? col + 1 : col;
                }
            }
        }
    }

    // ---- Quad argmax reduction (first-index tie-break), publish to smem -----
    #pragma unroll
    for (int rt = 0; rt < 2; rt++)
        #pragma unroll
        for (int h = 0; h < 2; h++)
            #pragma unroll
            for (int off = 1; off <= 2; off <<= 1) {
                float ov = __shfl_xor_sync(0xffffffffu, best[rt][h], off);
                int   oi = __shfl_xor_sync(0xffffffffu, bidx[rt][h], off);
                if (ov > best[rt][h] || (ov == best[rt][h] && oi < bidx[rt][h])) {
                    best[rt][h] = ov; bidx[rt][h] = oi;
                }
            }
    if ((lane & 3) == 0) {
        #pragma unroll
        for (int rt = 0; rt < 2; rt++)
            #pragma unroll
            for (int h = 0; h < 2; h++) {
                int lrow = wr0 + rt * 16 + g + h * 8;
                sbest[colhalf * 256 + lrow] = best[rt][h];
                sidx [colhalf * 256 + lrow] = bidx[rt][h];
            }
    }
    __syncthreads();

    if (tid < BM && labels_out) {
        float b0 = sbest[tid],        b1 = sbest[256 + tid];
        int   i0 = sidx[tid],         i1 = sidx[256 + tid];
        int   bi = (b1 > b0) ? i1 : i0;   // ties -> half 0 (lower col index)
        int   lab = proto_labels[bi];
        if (labels_as_int) ((int*)labels_out)[row0 + tid] = lab;
        else               labels_out[row0 + tid] = (float)lab;
    }
}

extern "C" void kernel_launch(void* const* d_in, const int* in_sizes, int n_in,
                              void* d_out, int out_size)
{
    const float* features     = (const float*)d_in[0];
    const float* protos       = (const float*)d_in[1];
    const int*   proto_labels = (const int*)d_in[2];

    const int       P = in_sizes[2];
    const int       D = in_sizes[1] / P;
    const long long N = (long long)in_sizes[0] / D;
    const size_t  npe = (size_t)N * (size_t)P;

    float* inv_out = nullptr;
    float* lab     = nullptr;
    int    lab_int = 0;
    if ((size_t)out_size >= npe) {
        inv_out = (float*)d_out;
        if ((size_t)out_size >= npe + (size_t)N) lab = (float*)d_out + npe;
    } else {
        lab = (float*)d_out;
        lab_int = 1;
    }

    convert_B<<<16, 256>>>(protos);
    cudaFuncSetAttribute(BaseProtonet_hmma,
                         cudaFuncAttributeMaxDynamicSharedMemorySize, SMEM_BYTES);
    BaseProtonet_hmma<<<(int)(N / BM), THREADS, SMEM_BYTES>>>(
        features, proto_labels, inv_out, lab, lab_int);
}

// round 16
// speedup vs baseline: 1.1748x; 1.1748x over previous
#include <cuda_runtime.h>
#include <cuda_fp16.h>
#include <cstdint>

// ---------------------------------------------------------------------------
// BaseProtonet via mma.sync (HMMA). FINAL (= round 14, best measured 103.1us):
//  - cross-term GEMM on tensor pipe via mma.sync m16n8k16, 3-pass fp16 hi/lo
//    split (hh+hl+lh; ll term <= ~2^-22 relative) -> rel_err ~1.1e-7
//  - B (prototypes) fp16 conversion + p2 norms hoisted to a tiny setup kernel
//    writing a __device__ scratch in the final swizzled layout; main kernel
//    cp.async-copies it linearly (L2-hot)
//  - BM=256 rows/CTA, 512 thr, 1 CTA/SM (RF-exact: 512x128 regs), warp tile
//    32 rows x 128 cols in two 64-col phases, register double-buffered B frags
//  - explicit MLP=8 A-tile LDG hoist ahead of all prologue work
//  - f2 norms via in-register 16-lane shuffle reduction (no gmem re-read)
//  - epilogue: inv_d = 64/(f2+p2-2*cross+64e-5), __stcs streaming stores,
//    pair-max argmax with exact first-index tie-breaking, labels via smem
//    combine of the two column halves.
// ---------------------------------------------------------------------------

#define SWZ128(o) ((o) ^ (((o) >> 3) & 0x70))

constexpr int Dk = 64;
constexpr int Pn = 256;
constexpr int BM = 256;
constexpr int THREADS = 512;

constexpr int OFF_AHI  = 0;          // 256 rows x 128B = 32768
constexpr int OFF_ALO  = 32768;
constexpr int OFF_BHI  = 65536;      // 32768
constexpr int OFF_BLO  = 98304;      // 32768
constexpr int OFF_P2   = 131072;     // 1024
constexpr int OFF_F2   = 132096;     // 1024
constexpr int OFF_SBST = 133120;     // 2048
constexpr int OFF_SIDX = 135168;     // 2048
constexpr int SMEM_BYTES = 137216;   // 1 CTA/SM (16 warps)

// global scratch: [0,32768) Bhi swizzled | [32768,65536) Blo swizzled | [65536,+1024) p2
__device__ __align__(128) unsigned char g_bconv[66560];

__device__ __forceinline__ uint32_t smem_u32(const void* p) {
    uint32_t a;
    asm("{ .reg .u64 t; cvta.to.shared.u64 t, %1; cvt.u32.u64 %0, t; }" : "=r"(a) : "l"(p));
    return a;
}
__device__ __forceinline__ uint64_t gmem_u64(const void* p) {
    uint64_t a;
    asm("cvta.to.global.u64 %0, %1;" : "=l"(a) : "l"(p));
    return a;
}
__device__ __forceinline__ void cp_async16(uint32_t sdst, uint64_t gsrc) {
    asm volatile("cp.async.cg.shared.global [%0], [%1], 16;" :: "r"(sdst), "l"(gsrc) : "memory");
}
__device__ __forceinline__ void ldsm_x4(uint32_t r[4], uint32_t addr) {
    asm volatile("ldmatrix.sync.aligned.m8n8.x4.shared.b16 {%0,%1,%2,%3}, [%4];"
                 : "=r"(r[0]), "=r"(r[1]), "=r"(r[2]), "=r"(r[3]) : "r"(addr));
}
__device__ __forceinline__ void mma16816(float c[4], const uint32_t a[4],
                                         uint32_t b0, uint32_t b1) {
    asm volatile("mma.sync.aligned.m16n8k16.row.col.f32.f16.f16.f32 "
                 "{%0,%1,%2,%3}, {%4,%5,%6,%7}, {%8,%9}, {%0,%1,%2,%3};"
                 : "+f"(c[0]), "+f"(c[1]), "+f"(c[2]), "+f"(c[3])
                 : "r"(a[0]), "r"(a[1]), "r"(a[2]), "r"(a[3]), "r"(b0), "r"(b1));
}
__device__ __forceinline__ uint32_t pack2(float x, float y) {
    __half hx = __float2half_rn(x), hy = __float2half_rn(y);
    return (uint32_t)__half_as_ushort(hx) | ((uint32_t)__half_as_ushort(hy) << 16);
}

// ---- Setup: convert protos -> fp16 hi/lo swizzled + p2 norms ---------------
__global__ void __launch_bounds__(256)
convert_B(const float* __restrict__ protos)
{
    const int tid = threadIdx.x;
    const int f4  = tid + blockIdx.x * 256;          // 0..4095
    {
        int row = f4 >> 4, k4 = f4 & 15;
        float4 v = ((const float4*)protos)[f4];
        float hx = __half2float(__float2half_rn(v.x));
        float hy = __half2float(__float2half_rn(v.y));
        float hz = __half2float(__float2half_rn(v.z));
        float hw = __half2float(__float2half_rn(v.w));
        uint2 hi = make_uint2(pack2(v.x, v.y), pack2(v.z, v.w));
        uint2 lo = make_uint2(pack2(v.x - hx, v.y - hy), pack2(v.z - hz, v.w - hw));
        uint32_t off = SWZ128((uint32_t)(row * 128 + k4 * 8));
        *(uint2*)(g_bconv + off)         = hi;
        *(uint2*)(g_bconv + 32768 + off) = lo;
    }
    if (blockIdx.x == 0) {   // p2 norms
        const float4* pr = (const float4*)protos + tid * 16;
        float q = 0.f;
        #pragma unroll
        for (int j = 0; j < 16; j++) {
            float4 v = pr[j];
            q = fmaf(v.x, v.x, q); q = fmaf(v.y, v.y, q);
            q = fmaf(v.z, v.z, q); q = fmaf(v.w, v.w, q);
        }
        ((float*)(g_bconv + 65536))[tid] = q;
    }
}

__global__ void __launch_bounds__(THREADS, 1)
BaseProtonet_hmma(const float* __restrict__ features,
                  const int*   __restrict__ proto_labels,
                  float* __restrict__ inv_out,
                  float* __restrict__ labels_out,
                  int labels_as_int)
{
    extern __shared__ char smem[];
    const uint32_t sbase = smem_u32(smem);
    const int tid  = threadIdx.x;
    const int wid  = tid >> 5;          // 0..15
    const int lane = tid & 31;

    float* p2s   = (float*)(smem + OFF_P2);
    float* f2s   = (float*)(smem + OFF_F2);
    float* sbest = (float*)(smem + OFF_SBST);   // [2][256]
    int*   sidx  = (int*)  (smem + OFF_SIDX);   // [2][256]

    const float* fb = features + (size_t)blockIdx.x * BM * Dk;

    // ---- Issue ALL A-tile loads first (cold DRAM, MLP=8 guaranteed) --------
    float4 va[8];
    {
        const float4* f4p = (const float4*)fb;
        #pragma unroll
        for (int i = 0; i < 8; i++)
            va[i] = f4p[tid + i * THREADS];
    }

    // ---- B + p2 copy (gmem scratch -> smem; L2-hot) -------------------------
    {
        const uint64_t gsrc = gmem_u64(g_bconv);
        #pragma unroll
        for (int i = 0; i < 8; i++)    // 64KB: Bhi+Blo contiguous
            cp_async16(sbase + OFF_BHI + i * 8192 + tid * 16,
                       gsrc + i * 8192 + tid * 16);
        if (tid < 64)                  // 1KB p2
            cp_async16(sbase + OFF_P2 + tid * 16, gsrc + 65536 + tid * 16);
        asm volatile("cp.async.commit_group;" ::: "memory");
    }

    // ---- Convert A tile (regs) -> fp16 hi/lo + f2 via shuffle reduction -----
    {
        #pragma unroll
        for (int i = 0; i < 8; i++) {
            int f4  = tid + i * THREADS;
            int row = f4 >> 4, k4 = f4 & 15;
            float4 v = va[i];
            float hx = __half2float(__float2half_rn(v.x));
            float hy = __half2float(__float2half_rn(v.y));
            float hz = __half2float(__float2half_rn(v.z));
            float hw = __half2float(__float2half_rn(v.w));
            uint2 hi = make_uint2(pack2(v.x, v.y), pack2(v.z, v.w));
            uint2 lo = make_uint2(pack2(v.x - hx, v.y - hy), pack2(v.z - hz, v.w - hw));
            uint32_t off = SWZ128((uint32_t)(row * 128 + k4 * 8));
            *(uint2*)(smem + OFF_AHI + off) = hi;
            *(uint2*)(smem + OFF_ALO + off) = lo;
            // row norm: 16 consecutive tids own one row
            float s = v.x * v.x;
            s = fmaf(v.y, v.y, s);
            s = fmaf(v.z, v.z, s);
            s = fmaf(v.w, v.w, s);
            #pragma unroll
            for (int o = 8; o > 0; o >>= 1)
                s += __shfl_xor_sync(0xffffffffu, s, o);
            if ((tid & 15) == 0) f2s[row] = s;
        }
    }
    asm volatile("cp.async.wait_group 0;" ::: "memory");
    __syncthreads();

    // ---- Warp tiling: 8 row-groups x 2 col-halves ---------------------------
    const int wr0     = (wid >> 1) * 32;     // 0..224
    const int colhalf = wid & 1;
    const int g       = lane >> 2;
    const int q       = lane & 3;

    float srow[2][2];
    #pragma unroll
    for (int rt = 0; rt < 2; rt++) {
        srow[rt][0] = f2s[wr0 + rt * 16 + g]     + 64.f * 1e-5f;
        srow[rt][1] = f2s[wr0 + rt * 16 + g + 8] + 64.f * 1e-5f;
    }

    float best[2][2] = {{-1e30f, -1e30f}, {-1e30f, -1e30f}};
    int   bidx[2][2] = {{0, 0}, {0, 0}};

    const size_t row0 = (size_t)blockIdx.x * BM;

    float* outbase[2];
    #pragma unroll
    for (int rt = 0; rt < 2; rt++)
        outbase[rt] = inv_out + (row0 + wr0 + rt * 16 + g) * Pn + q * 2;

    const int bn_lane = (lane & 7) + ((lane >> 4) & 1) * 8;
    const int bc_lane = (lane >> 3) & 1;
    const int arow_lo = lane & 15;
    const int achnk   = lane >> 4;
    const bool do_out = (inv_out != nullptr);

    #pragma unroll
    for (int ph = 0; ph < 2; ph++) {
        const int colbase = colhalf * 128 + ph * 64;
        float acc[2][8][4];
        #pragma unroll
        for (int rt = 0; rt < 2; rt++)
            #pragma unroll
            for (int t = 0; t < 8; t++)
                #pragma unroll
                for (int j = 0; j < 4; j++) acc[rt][t][j] = 0.f;

        // ---- preload A (ks=0) and B (it=0) ----------------------------------
        uint32_t ahi[2][4], alo[2][4];
        uint32_t bh[2][4], bl[2][4];
        #pragma unroll
        for (int rt = 0; rt < 2; rt++) {
            int arow = wr0 + rt * 16 + arow_lo;
            uint32_t off = SWZ128((uint32_t)(arow * 128 + achnk * 16));
            ldsm_x4(ahi[rt], sbase + OFF_AHI + off);
            ldsm_x4(alo[rt], sbase + OFF_ALO + off);
        }
        {
            int n = colbase + bn_lane;
            uint32_t off = SWZ128((uint32_t)(n * 128 + bc_lane * 16));
            ldsm_x4(bh[0], sbase + OFF_BHI + off);
            ldsm_x4(bl[0], sbase + OFF_BLO + off);
        }

        // ---- flattened ks x tp loop with B double-buffer --------------------
        #pragma unroll
        for (int it = 0; it < 16; it++) {
            const int ks  = it >> 2;
            const int tp  = it & 3;
            const int cur = it & 1;
            const int nxt = cur ^ 1;
            if (it < 15) {
                const int ks2 = (it + 1) >> 2;
                const int tp2 = (it + 1) & 3;
                int n     = colbase + tp2 * 16 + bn_lane;
                int chunk = 2 * ks2 + bc_lane;
                uint32_t off = SWZ128((uint32_t)(n * 128 + chunk * 16));
                ldsm_x4(bh[nxt], sbase + OFF_BHI + off);
                ldsm_x4(bl[nxt], sbase + OFF_BLO + off);
            }
            const int t0 = tp * 2, t1 = t0 + 1;
            #pragma unroll
            for (int rt = 0; rt < 2; rt++) {
                mma16816(acc[rt][t0], ahi[rt], bh[cur][0], bh[cur][1]);
                mma16816(acc[rt][t1], ahi[rt], bh[cur][2], bh[cur][3]);
                mma16816(acc[rt][t0], ahi[rt], bl[cur][0], bl[cur][1]);
                mma16816(acc[rt][t1], ahi[rt], bl[cur][2], bl[cur][3]);
                mma16816(acc[rt][t0], alo[rt], bh[cur][0], bh[cur][1]);
                mma16816(acc[rt][t1], alo[rt], bh[cur][2], bh[cur][3]);
            }
            if (tp == 3 && ks < 3) {
                #pragma unroll
                for (int rt = 0; rt < 2; rt++) {
                    int arow = wr0 + rt * 16 + arow_lo;
                    uint32_t off = SWZ128((uint32_t)(arow * 128 + (2 * (ks + 1) + achnk) * 16));
                    ldsm_x4(ahi[rt], sbase + OFF_AHI + off);
                    ldsm_x4(alo[rt], sbase + OFF_ALO + off);
                }
            }
        }

        // ---- Epilogue for this phase: t outer, rt inner ----------------------
        #pragma unroll
        for (int t = 0; t < 8; t++) {
            const int col = colbase + t * 8 + q * 2;
            const float2 p2v = *(const float2*)&p2s[col];
            #pragma unroll
            for (int rt = 0; rt < 2; rt++) {
                float v0 = __fdividef(64.f, fmaf(-2.f, acc[rt][t][0], srow[rt][0] + p2v.x));
                float v1 = __fdividef(64.f, fmaf(-2.f, acc[rt][t][1], srow[rt][0] + p2v.y));
                float v2 = __fdividef(64.f, fmaf(-2.f, acc[rt][t][2], srow[rt][1] + p2v.x));
                float v3 = __fdividef(64.f, fmaf(-2.f, acc[rt][t][3], srow[rt][1] + p2v.y));
                if (do_out) {
                    __stcs((float2*)(outbase[rt] + colbase + t * 8),
                           make_float2(v0, v1));
                    __stcs((float2*)(outbase[rt] + 8 * Pn + colbase + t * 8),
                           make_float2(v2, v3));
                }
                float m01 = fmaxf(v0, v1);
                if (m01 > best[rt][0]) {
                    best[rt][0] = m01;
                    bidx[rt][0] = (v1 > v0) ? col + 1 : col;
                }
                float m23 = fmaxf(v2, v3);
                if (m23 > best[rt][1]) {
                    best[rt][1] = m23;
                    bidx[rt][1] = (v3 > v2) ? col + 1 : col;
                }
            }
        }
    }

    // ---- Quad argmax reduction (first-index tie-break), publish to smem -----
    #pragma unroll
    for (int rt = 0; rt < 2; rt++)
        #pragma unroll
        for (int h = 0; h < 2; h++)
            #pragma unroll
            for (int off = 1; off <= 2; off <<= 1) {
                float ov = __shfl_xor_sync(0xffffffffu, best[rt][h], off);
                int   oi = __shfl_xor_sync(0xffffffffu, bidx[rt][h], off);
                if (ov > best[rt][h] || (ov == best[rt][h] && oi < bidx[rt][h])) {
                    best[rt][h] = ov; bidx[rt][h] = oi;
                }
            }
    if ((lane & 3) == 0) {
        #pragma unroll
        for (int rt = 0; rt < 2; rt++)
            #pragma unroll
            for (int h = 0; h < 2; h++) {
                int lrow = wr0 + rt * 16 + g + h * 8;
                sbest[colhalf * 256 + lrow] = best[rt][h];
                sidx [colhalf * 256 + lrow] = bidx[rt][h];
            }
    }
    __syncthreads();

    if (tid < BM && labels_out) {
        float b0 = sbest[tid],        b1 = sbest[256 + tid];
        int   i0 = sidx[tid],         i1 = sidx[256 + tid];
        int   bi = (b1 > b0) ? i1 : i0;   // ties -> half 0 (lower col index)
        int   lab = proto_labels[bi];
        if (labels_as_int) ((int*)labels_out)[row0 + tid] = lab;
        else               labels_out[row0 + tid] = (float)lab;
    }
}

extern "C" void kernel_launch(void* const* d_in, const int* in_sizes, int n_in,
                              void* d_out, int out_size)
{
    const float* features     = (const float*)d_in[0];
    const float* protos       = (const float*)d_in[1];
    const int*   proto_labels = (const int*)d_in[2];

    const int       P = in_sizes[2];
    const int       D = in_sizes[1] / P;
    const long long N = (long long)in_sizes[0] / D;
    const size_t  npe = (size_t)N * (size_t)P;

    float* inv_out = nullptr;
    float* lab     = nullptr;
    int    lab_int = 0;
    if ((size_t)out_size >= npe) {
        inv_out = (float*)d_out;
        if ((size_t)out_size >= npe + (size_t)N) lab = (float*)d_out + npe;
    } else {
        lab = (float*)d_out;
        lab_int = 1;
    }

    convert_B<<<16, 256>>>(protos);
    cudaFuncSetAttribute(BaseProtonet_hmma,
                         cudaFuncAttributeMaxDynamicSharedMemorySize, SMEM_BYTES);
    BaseProtonet_hmma<<<(int)(N / BM), THREADS, SMEM_BYTES>>>(
        features, proto_labels, inv_out, lab, lab_int);
}